// round 14
// baseline (speedup 1.0000x reference)
#include <cuda_runtime.h>
#include <math.h>

#define N 8192
#define D 64
#define ALPHA 0.2f
#define NB 16384
#define SHIFT 18           // bucket = top 14 bits of order-flipped float key
#define NBLK 130
#define NTHR 1024
#define GSIZE (NBLK * NTHR)

// ---------------- scratch (device globals; no allocation allowed) -----------
__device__ float    g_h[N * D];        // projected features (2 MB)
__device__ float    g_hsT[D * N];      // h, sorted order, TRANSPOSED [d][k] (2 MB)
__device__ float    g_f1[N];
__device__ float    g_f2[N];
__device__ unsigned g_ukey[N];
__device__ __align__(16) int g_hist[NB];
__device__ int      g_start[NB + 1];
__device__ int      g_cursor[NB];
__device__ unsigned g_bkey[N];
__device__ int      g_bidx[N];
__device__ float    g_f2s[N];          // f2 sorted ascending
__device__ int      g_ord[N];          // sorted position -> original index
__device__ float    g_ehi[N];          // e^{f2s}
__device__ float    g_elo[N];          // e^{ALPHA*f2s}
__device__ int      g_p[N];            // per-row split point
__device__ float    g_c[N];            // per-row e^{(ALPHA-1) f1}
__device__ float    g_SThi[D * N];     // suffix sums, transposed [d][k] (2 MB)
__device__ float    g_STlo[D * N];     // prefix sums, transposed [d][k] (2 MB)
__device__ float    g_Shi[(N + 1) * D];// SUFFIX sums [k][d]; row N = 0
__device__ float    g_Plo[(N + 1) * D];// PREFIX sums shifted [k][d]; row 0 = 0
__device__ float    g_pshis[N + 1];    // scalar suffix of e^{f2};   [N]=0
__device__ float    g_pslos[N + 1];    // scalar prefix of e^{a f2}; [0]=0

// ---------------- software grid barrier -------------------------------------
__device__ unsigned g_bar_arrive = 0;
__device__ unsigned g_bar_gen    = 0;

__device__ __forceinline__ void gbar(unsigned& gen) {
    __syncthreads();
    if (threadIdx.x == 0) {
        __threadfence();
        unsigned my = gen;
        if (atomicAdd(&g_bar_arrive, 1) == NBLK - 1) {
            g_bar_arrive = 0;          // reset BEFORE release (ordered by fence)
            __threadfence();
            atomicAdd(&g_bar_gen, 1);
        } else {
            while (*(volatile unsigned*)&g_bar_gen == my) __nanosleep(32);
        }
        __threadfence();
        gen = my + 1;
    }
    __syncthreads();
}

// ---------------- the single persistent kernel ------------------------------
__global__ void __launch_bounds__(NTHR, 1) k_fused(
    const float* __restrict__ x,  const float* __restrict__ Wt,
    const float* __restrict__ a1, const float* __restrict__ b1,
    const float* __restrict__ a2, const float* __restrict__ b2,
    float* __restrict__ out)
{
    __shared__ __align__(16) char sbuf[35328];   // A: sWt|sxT|sa1|sa2|sred ; D2/F tile
    __shared__ int    sord[64];
    __shared__ int    sint[32];
    __shared__ double sdbl[32];

    const int t    = threadIdx.x;
    const int b    = blockIdx.x;
    const int gtid = b * NTHR + t;
    const int lane = t & 31, warp = t >> 5;
    unsigned gen = *(volatile unsigned*)&g_bar_gen;   // per-launch snapshot

    // ===== Phase A: projection h = x*Wt, scores f1/f2, key + histogram ======
    // sxT[k][r] (pad 68): per k-iter the x-quad is a 16B warp-broadcast and
    // the w-read is conflict-free 128B — ~2 LDS-cyc per 4 FMA.
    if (b < 128) {
        float* sWt   = (float*)sbuf;                  // [64][64]  16384 B
        float* sxT   = (float*)(sbuf + 16384);        // [64][68]  17408 B
        float* sa1   = (float*)(sbuf + 33792);        // 256 B
        float* sa2   = (float*)(sbuf + 34048);        // 256 B
        float* sred1 = (float*)(sbuf + 34304);        // [32 warps][4 rows]
        float* sred2 = (float*)(sbuf + 34816);
        const int row0 = b * 64;

        for (int i = t; i < D * D; i += NTHR) sWt[i] = Wt[i];
        for (int i = t; i < D * D; i += NTHR) {
            int r = i >> 6, k = i & 63;
            sxT[k * 68 + r] = x[row0 * D + i];
        }
        if (t < D) { sa1[t] = a1[t]; sa2[t] = a2[t]; }
        __syncthreads();

        const int c  = t & 63;                  // output column
        const int rq = (t >> 6) * 4;            // row-quad base (0,4,...,60)

        float acc0 = 0.f, acc1 = 0.f, acc2 = 0.f, acc3 = 0.f;
        #pragma unroll 16
        for (int k = 0; k < D; k++) {
            float  wv = sWt[k * D + c];                    // conflict-free
            float4 xv = *(const float4*)&sxT[k * 68 + rq]; // 16B broadcast
            acc0 = fmaf(xv.x, wv, acc0);
            acc1 = fmaf(xv.y, wv, acc1);
            acc2 = fmaf(xv.z, wv, acc2);
            acc3 = fmaf(xv.w, wv, acc3);
        }
        g_h[(row0 + rq + 0) * D + c] = acc0;    // coalesced per row
        g_h[(row0 + rq + 1) * D + c] = acc1;
        g_h[(row0 + rq + 2) * D + c] = acc2;
        g_h[(row0 + rq + 3) * D + c] = acc3;

        float a1c = sa1[c], a2c = sa2[c];
        float q10 = acc0 * a1c, q11 = acc1 * a1c, q12 = acc2 * a1c, q13 = acc3 * a1c;
        float q20 = acc0 * a2c, q21 = acc1 * a2c, q22 = acc2 * a2c, q23 = acc3 * a2c;
        #pragma unroll
        for (int off = 16; off > 0; off >>= 1) {
            q10 += __shfl_down_sync(0xffffffffu, q10, off);
            q11 += __shfl_down_sync(0xffffffffu, q11, off);
            q12 += __shfl_down_sync(0xffffffffu, q12, off);
            q13 += __shfl_down_sync(0xffffffffu, q13, off);
            q20 += __shfl_down_sync(0xffffffffu, q20, off);
            q21 += __shfl_down_sync(0xffffffffu, q21, off);
            q22 += __shfl_down_sync(0xffffffffu, q22, off);
            q23 += __shfl_down_sync(0xffffffffu, q23, off);
        }
        if (lane == 0) {
            sred1[warp * 4 + 0] = q10; sred1[warp * 4 + 1] = q11;
            sred1[warp * 4 + 2] = q12; sred1[warp * 4 + 3] = q13;
            sred2[warp * 4 + 0] = q20; sred2[warp * 4 + 1] = q21;
            sred2[warp * 4 + 2] = q22; sred2[warp * 4 + 3] = q23;
        }
        __syncthreads();
        if (t < 64) {
            int rg = t >> 2, rr = t & 3;        // row = rg*4 + rr
            int w0 = rg * 2, w1 = w0 + 1;       // the two warps covering c 0..63
            float f1v = sred1[w0 * 4 + rr] + sred1[w1 * 4 + rr] + b1[0];
            float f2v = sred2[w0 * 4 + rr] + sred2[w1 * 4 + rr] + b2[0];
            int row = row0 + rg * 4 + rr;
            g_f1[row] = f1v;
            g_f2[row] = f2v;
            unsigned u = __float_as_uint(f2v);
            u ^= (u >> 31) ? 0xFFFFFFFFu : 0x80000000u;
            g_ukey[row] = u;
            atomicAdd(&g_hist[u >> SHIFT], 1);
        }
    }
    gbar(gen);

    // ===== Phase B: full histogram exclusive scan, ONE block ================
    if (b == 0) {
        int base = t * 16;
        int loc[16];
        int sum = 0;
        const uint4* H4 = (const uint4*)(g_hist + base);
        #pragma unroll
        for (int q = 0; q < 4; q++) {
            uint4 hv = H4[q];
            loc[q * 4 + 0] = sum; sum += (int)hv.x;
            loc[q * 4 + 1] = sum; sum += (int)hv.y;
            loc[q * 4 + 2] = sum; sum += (int)hv.z;
            loc[q * 4 + 3] = sum; sum += (int)hv.w;
        }
        int w = sum;
        #pragma unroll
        for (int off = 1; off < 32; off <<= 1) {
            int o = __shfl_up_sync(0xffffffffu, w, off);
            if (lane >= off) w += o;
        }
        if (lane == 31) sint[warp] = w;
        __syncthreads();
        if (t < 32) {
            int v = sint[t];
            #pragma unroll
            for (int off = 1; off < 32; off <<= 1) {
                int o = __shfl_up_sync(0xffffffffu, v, off);
                if (t >= off) v += o;
            }
            sint[t] = v;
        }
        __syncthreads();
        int excl = (w - sum) + (warp ? sint[warp - 1] : 0);
        #pragma unroll
        for (int j = 0; j < 16; j++) {
            int s = excl + loc[j];
            g_start[base + j]  = s;
            g_cursor[base + j] = s;
        }
        if (t == 0) g_start[NB] = N;
    }
    gbar(gen);

    // ===== Phase C: scatter (128 blocks x 64) + re-zero histogram ===========
    if (b < 128) {
        if (t < 64) {
            int i = b * 64 + t;
            unsigned u = g_ukey[i];
            int pos = atomicAdd(&g_cursor[u >> SHIFT], 1);
            g_bkey[pos] = u;
            g_bidx[pos] = i;
        } else if (t < 192) {
            g_hist[b * 128 + (t - 64)] = 0;
        }
    }
    gbar(gen);

    // ===== Phase D: rank within bucket (16 threads/element) =================
    {
        int el  = gtid >> 4;           // 0..8319
        int seg = gtid & 15;
        if (el < N) {
            unsigned u = g_bkey[el];
            int i  = g_bidx[el];
            int bk = u >> SHIFT;
            int st = g_start[bk], en = g_start[bk + 1];
            int rank = 0;
            for (int j = st + seg; j < en; j += 16) {
                unsigned kj = g_bkey[j];
                rank += (kj < u) || (kj == u && g_bidx[j] < i);
            }
            #pragma unroll
            for (int off = 8; off > 0; off >>= 1)
                rank += __shfl_down_sync(0xffffffffu, rank, off, 16);
            if (seg == 0) {
                rank += st;
                float f2v = g_f2[i];
                g_f2s[rank] = f2v;
                g_ord[rank] = i;
                g_ehi[rank] = expf(f2v);
                g_elo[rank] = expf(ALPHA * f2v);
            }
        }
    }
    gbar(gen);

    // ===== Phase D2: smem-tiled permuted transpose h -> g_hsT[d][k] =========
    if (b < 128) {
        float* tile = (float*)sbuf;                // [64][65]
        const int k0 = b * 64;
        if (t < 64) sord[t] = g_ord[k0 + t];
        __syncthreads();
        {
            int kk = t >> 4, l4 = (t & 15) * 4;    // coalesced-ish row load
            float4 hv = *(const float4*)&g_h[sord[kk] * D + l4];
            tile[kk * 65 + l4 + 0] = hv.x;
            tile[kk * 65 + l4 + 1] = hv.y;
            tile[kk * 65 + l4 + 2] = hv.z;
            tile[kk * 65 + l4 + 3] = hv.w;
        }
        __syncthreads();
        {
            int d = t >> 4, kq = (t & 15) * 4;     // coalesced write along k
            float4 ov = make_float4(tile[(kq + 0) * 65 + d],
                                    tile[(kq + 1) * 65 + d],
                                    tile[(kq + 2) * 65 + d],
                                    tile[(kq + 3) * 65 + d]);
            *(float4*)&g_hsT[d * N + k0 + kq] = ov;
        }
    }
    gbar(gen);

    // ===== Phase E: 130 directional fp64-accum scans -> TRANSPOSED fp32 =====
    // hi blocks (b<64 dims, b==128 scalar): SUFFIX -> g_SThi / g_pshis
    // lo blocks (64..127, b==129 scalar):  PREFIX -> g_STlo / g_pslos
    if (b < 130) {
        bool scalar = (b >= 128);
        bool hi = (b < 64) || (b == 128);
        int dim = scalar ? 0 : (hi ? b : b - 64);
        const float* e    = hi ? g_ehi : g_elo;
        const float* hrow = g_hsT + (size_t)dim * N;

        int k0 = t * 8;
        float ev[8], hv[8];
        *(float4*)&ev[0] = *(const float4*)&e[k0];       // vectorized loads
        *(float4*)&ev[4] = *(const float4*)&e[k0 + 4];
        if (!scalar) {
            *(float4*)&hv[0] = *(const float4*)&hrow[k0];
            *(float4*)&hv[4] = *(const float4*)&hrow[k0 + 4];
        } else {
            #pragma unroll
            for (int j = 0; j < 8; j++) hv[j] = 1.f;
        }

        double v[8];
        double run = 0.0;
        if (hi) {                      // local SUFFIX within chunk (j desc)
            #pragma unroll
            for (int j = 7; j >= 0; j--) {
                run += (double)ev[j] * (double)hv[j];
                v[j] = run;
            }
        } else {                       // local PREFIX within chunk (j asc)
            #pragma unroll
            for (int j = 0; j < 8; j++) {
                run += (double)ev[j] * (double)hv[j];
                v[j] = run;
            }
        }
        double w = run;
        if (hi) {                      // reverse inclusive scan across lanes
            #pragma unroll
            for (int off = 1; off < 32; off <<= 1) {
                double o = __shfl_down_sync(0xffffffffu, w, off);
                if (lane + off < 32) w += o;
            }
            if (lane == 0) sdbl[warp] = w;
            __syncthreads();
            if (t < 32) {
                double x2 = sdbl[t];
                #pragma unroll
                for (int off = 1; off < 32; off <<= 1) {
                    double o = __shfl_down_sync(0xffffffffu, x2, off);
                    if (t + off < 32) x2 += o;
                }
                sdbl[t] = x2;
            }
            __syncthreads();
            double base = (w - run) + (warp < 31 ? sdbl[warp + 1] : 0.0);
            if (scalar) {
                #pragma unroll
                for (int j = 0; j < 8; j++) g_pshis[k0 + j] = (float)(base + v[j]);
                if (t == 0) g_pshis[N] = 0.f;
            } else {
                float4 s0 = make_float4((float)(base + v[0]), (float)(base + v[1]),
                                        (float)(base + v[2]), (float)(base + v[3]));
                float4 s1 = make_float4((float)(base + v[4]), (float)(base + v[5]),
                                        (float)(base + v[6]), (float)(base + v[7]));
                *(float4*)&g_SThi[(size_t)dim * N + k0]     = s0;
                *(float4*)&g_SThi[(size_t)dim * N + k0 + 4] = s1;
            }
        } else {                       // forward inclusive scan across lanes
            #pragma unroll
            for (int off = 1; off < 32; off <<= 1) {
                double o = __shfl_up_sync(0xffffffffu, w, off);
                if (lane >= off) w += o;
            }
            if (lane == 31) sdbl[warp] = w;
            __syncthreads();
            if (t < 32) {
                double x2 = sdbl[t];
                #pragma unroll
                for (int off = 1; off < 32; off <<= 1) {
                    double o = __shfl_up_sync(0xffffffffu, x2, off);
                    if (t >= off) x2 += o;
                }
                sdbl[t] = x2;
            }
            __syncthreads();
            double base = (w - run) + (warp ? sdbl[warp - 1] : 0.0);
            if (scalar) {              // shifted: pslos[k+1] = incl prefix
                #pragma unroll
                for (int j = 0; j < 8; j++) g_pslos[k0 + j + 1] = (float)(base + v[j]);
                if (t == 0) g_pslos[0] = 0.f;
            } else {                   // unshifted transposed; shift applied in F
                float4 s0 = make_float4((float)(base + v[0]), (float)(base + v[1]),
                                        (float)(base + v[2]), (float)(base + v[3]));
                float4 s1 = make_float4((float)(base + v[4]), (float)(base + v[5]),
                                        (float)(base + v[6]), (float)(base + v[7]));
                *(float4*)&g_STlo[(size_t)dim * N + k0]     = s0;
                *(float4*)&g_STlo[(size_t)dim * N + k0 + 4] = s1;
            }
        }

        // per-row binary search (idle-lane work, independent of scan stores)
        if (t < 64 && b < 128) {
            int row = b * 64 + t;
            float f1 = g_f1[row];
            float tt = -f1;
            int lo = 0, hi2 = N;           // p = #{ f2s <= -f1 }
            while (lo < hi2) {
                int mid = (lo + hi2) >> 1;
                if (g_f2s[mid] <= tt) lo = mid + 1; else hi2 = mid;
            }
            g_p[row] = lo;
            g_c[row] = expf((ALPHA - 1.0f) * f1);
        }
    }
    gbar(gen);

    // ===== Phase F: tiled transpose [d][k] -> [k][d] (+ zero pad rows) ======
    {
        if (b == 128 && t < 64) g_Shi[N * D + t] = 0.f;   // Shi row N
        if (b == 129 && t < 64) g_Plo[t] = 0.f;           // Plo row 0
        float* tile = (float*)sbuf;                       // [64][65]
        for (int tile_id = b; tile_id < 256; tile_id += NBLK) {
            bool hiA = tile_id < 128;
            int k0 = (tile_id & 127) * 64;
            const float* src = hiA ? g_SThi : g_STlo;
            __syncthreads();                              // reuse guard
            {
                int d = t >> 4, kq = (t & 15) * 4;        // coalesced read along k
                float4 sv = *(const float4*)&src[(size_t)d * N + k0 + kq];
                tile[(kq + 0) * 65 + d] = sv.x;
                tile[(kq + 1) * 65 + d] = sv.y;
                tile[(kq + 2) * 65 + d] = sv.z;
                tile[(kq + 3) * 65 + d] = sv.w;
            }
            __syncthreads();
            {
                int kk = t >> 4, dq = (t & 15) * 4;       // coalesced write along d
                float4 ov = make_float4(tile[kk * 65 + dq + 0],
                                        tile[kk * 65 + dq + 1],
                                        tile[kk * 65 + dq + 2],
                                        tile[kk * 65 + dq + 3]);
                if (hiA) *(float4*)&g_Shi[(k0 + kk) * D + dq]     = ov;
                else     *(float4*)&g_Plo[(k0 + kk + 1) * D + dq] = ov;
            }
        }
    }
    gbar(gen);

    // ===== Phase G: branchless fp32 combine + ELU ===========================
    {
        const int d = gtid & 63;           // invariant: GSIZE % 64 == 0
        for (int idx = gtid; idx < N * D; idx += GSIZE) {
            int row = idx >> 6;
            int   p = g_p[row];
            float c = g_c[row];
            float num = g_Shi[p * D + d] + c * g_Plo[p * D + d];
            float den = g_pshis[p]       + c * g_pslos[p];
            float v = __fdividef(num, den);
            out[idx] = (v > 0.f) ? v : expm1f(v);
        }
    }
}

// ---------------- launch ----------------------------------------------------
extern "C" void kernel_launch(void* const* d_in, const int* in_sizes, int n_in,
                              void* d_out, int out_size) {
    const float* x  = (const float*)d_in[0];
    const float* Wt = (const float*)d_in[1];
    const float* a1 = (const float*)d_in[2];
    const float* b1 = (const float*)d_in[3];
    const float* a2 = (const float*)d_in[4];
    const float* b2 = (const float*)d_in[5];
    float* out = (float*)d_out;

    k_fused<<<NBLK, NTHR>>>(x, Wt, a1, b1, a2, b2, out);
}

// round 15
// speedup vs baseline: 1.2936x; 1.2936x over previous
#include <cuda_runtime.h>
#include <math.h>

#define N 8192
#define D 64
#define ALPHA 0.2f
#define NB 16384
#define SHIFT 18           // bucket = top 14 bits of order-flipped float key
#define NBLK 130
#define NTHR 1024
#define GSIZE (NBLK * NTHR)

// ---------------- scratch (device globals; no allocation allowed) -----------
__device__ float    g_h[N * D];        // projected features (2 MB)
__device__ float    g_hsT[D * N];      // h, sorted order, TRANSPOSED [d][k] (2 MB)
__device__ float    g_f1[N];
__device__ float    g_f2[N];
__device__ unsigned g_ukey[N];
__device__ int      g_hist[NB];
__device__ int      g_incl[NB];        // block-local inclusive scan of hist
__device__ int      g_btot[16];
__device__ int      g_start[NB + 1];
__device__ int      g_cursor[NB];
__device__ unsigned g_bkey[N];
__device__ int      g_bidx[N];
__device__ float    g_f2s[N];          // f2 sorted ascending
__device__ int      g_ord[N];          // sorted position -> original index
__device__ float    g_ehi[N];          // e^{f2s}
__device__ float    g_elo[N];          // e^{ALPHA*f2s}
__device__ int      g_p[N];            // per-row split point
__device__ float    g_c[N];            // per-row e^{(ALPHA-1) f1}
__device__ float    g_SThi[D * N];     // suffix sums, transposed [d][k] (2 MB)
__device__ float    g_STlo[D * N];     // prefix sums, transposed [d][k] (2 MB)
__device__ float    g_Shi[(N + 1) * D];// SUFFIX sums [k][d]; row N = 0
__device__ float    g_Plo[(N + 1) * D];// PREFIX sums shifted [k][d]; row 0 = 0
__device__ float    g_pshis[N + 1];    // scalar suffix of e^{f2};   [N]=0
__device__ float    g_pslos[N + 1];    // scalar prefix of e^{a f2}; [0]=0

// ---------------- software grid barrier -------------------------------------
__device__ unsigned g_bar_arrive = 0;
__device__ unsigned g_bar_gen    = 0;

__device__ __forceinline__ void gbar(unsigned& gen) {
    __syncthreads();
    if (threadIdx.x == 0) {
        __threadfence();
        unsigned my = gen;
        if (atomicAdd(&g_bar_arrive, 1) == NBLK - 1) {
            g_bar_arrive = 0;          // reset BEFORE release (ordered by fence)
            __threadfence();
            atomicAdd(&g_bar_gen, 1);
        } else {
            while (*(volatile unsigned*)&g_bar_gen == my) __nanosleep(32);
        }
        __threadfence();
        gen = my + 1;
    }
    __syncthreads();
}

// ---------------- the single persistent kernel ------------------------------
__global__ void __launch_bounds__(NTHR, 1) k_fused(
    const float* __restrict__ x,  const float* __restrict__ Wt,
    const float* __restrict__ a1, const float* __restrict__ b1,
    const float* __restrict__ a2, const float* __restrict__ b2,
    float* __restrict__ out)
{
    __shared__ __align__(16) char sbuf[35328];   // A: sWt|sxT|sa1|sa2|sred ; D2/F tile
    __shared__ int    sord[64];
    __shared__ int    sint[32];
    __shared__ double sdbl[32];

    const int t    = threadIdx.x;
    const int b    = blockIdx.x;
    const int gtid = b * NTHR + t;
    const int lane = t & 31, warp = t >> 5;
    unsigned gen = *(volatile unsigned*)&g_bar_gen;   // per-launch snapshot

    // ===== Phase A: projection h = x*Wt, scores f1/f2, key + histogram ======
    // sxT[k][r] (pad 68): per k-iter the x-quad is a 16B warp-broadcast and
    // the w-read is conflict-free 128B — ~2 LDS-cyc per 4 FMA.
    if (b < 128) {
        float* sWt   = (float*)sbuf;                  // [64][64]  16384 B
        float* sxT   = (float*)(sbuf + 16384);        // [64][68]  17408 B
        float* sa1   = (float*)(sbuf + 33792);        // 256 B
        float* sa2   = (float*)(sbuf + 34048);        // 256 B
        float* sred1 = (float*)(sbuf + 34304);        // [32 warps][4 rows]
        float* sred2 = (float*)(sbuf + 34816);
        const int row0 = b * 64;

        for (int i = t; i < D * D; i += NTHR) sWt[i] = Wt[i];
        for (int i = t; i < D * D; i += NTHR) {
            int r = i >> 6, k = i & 63;
            sxT[k * 68 + r] = x[row0 * D + i];
        }
        if (t < D) { sa1[t] = a1[t]; sa2[t] = a2[t]; }
        __syncthreads();

        const int c  = t & 63;                  // output column
        const int rq = (t >> 6) * 4;            // row-quad base (0,4,...,60)

        float acc0 = 0.f, acc1 = 0.f, acc2 = 0.f, acc3 = 0.f;
        #pragma unroll 16
        for (int k = 0; k < D; k++) {
            float  wv = sWt[k * D + c];                    // conflict-free
            float4 xv = *(const float4*)&sxT[k * 68 + rq]; // 16B broadcast
            acc0 = fmaf(xv.x, wv, acc0);
            acc1 = fmaf(xv.y, wv, acc1);
            acc2 = fmaf(xv.z, wv, acc2);
            acc3 = fmaf(xv.w, wv, acc3);
        }
        g_h[(row0 + rq + 0) * D + c] = acc0;    // coalesced per row
        g_h[(row0 + rq + 1) * D + c] = acc1;
        g_h[(row0 + rq + 2) * D + c] = acc2;
        g_h[(row0 + rq + 3) * D + c] = acc3;

        float a1c = sa1[c], a2c = sa2[c];
        float q10 = acc0 * a1c, q11 = acc1 * a1c, q12 = acc2 * a1c, q13 = acc3 * a1c;
        float q20 = acc0 * a2c, q21 = acc1 * a2c, q22 = acc2 * a2c, q23 = acc3 * a2c;
        #pragma unroll
        for (int off = 16; off > 0; off >>= 1) {
            q10 += __shfl_down_sync(0xffffffffu, q10, off);
            q11 += __shfl_down_sync(0xffffffffu, q11, off);
            q12 += __shfl_down_sync(0xffffffffu, q12, off);
            q13 += __shfl_down_sync(0xffffffffu, q13, off);
            q20 += __shfl_down_sync(0xffffffffu, q20, off);
            q21 += __shfl_down_sync(0xffffffffu, q21, off);
            q22 += __shfl_down_sync(0xffffffffu, q22, off);
            q23 += __shfl_down_sync(0xffffffffu, q23, off);
        }
        if (lane == 0) {
            sred1[warp * 4 + 0] = q10; sred1[warp * 4 + 1] = q11;
            sred1[warp * 4 + 2] = q12; sred1[warp * 4 + 3] = q13;
            sred2[warp * 4 + 0] = q20; sred2[warp * 4 + 1] = q21;
            sred2[warp * 4 + 2] = q22; sred2[warp * 4 + 3] = q23;
        }
        __syncthreads();
        if (t < 64) {
            int rg = t >> 2, rr = t & 3;        // row = rg*4 + rr
            int w0 = rg * 2, w1 = w0 + 1;       // the two warps covering c 0..63
            float f1v = sred1[w0 * 4 + rr] + sred1[w1 * 4 + rr] + b1[0];
            float f2v = sred2[w0 * 4 + rr] + sred2[w1 * 4 + rr] + b2[0];
            int row = row0 + rg * 4 + rr;
            g_f1[row] = f1v;
            g_f2[row] = f2v;
            unsigned u = __float_as_uint(f2v);
            u ^= (u >> 31) ? 0xFFFFFFFFu : 0x80000000u;
            g_ukey[row] = u;
            atomicAdd(&g_hist[u >> SHIFT], 1);
        }
    }
    gbar(gen);

    // ===== Phase B1: per-block inclusive scan of histogram (16 blocks) ======
    if (b < 16) {
        int i = b * NTHR + t;
        int v = g_hist[i];
        int s = v;
        #pragma unroll
        for (int off = 1; off < 32; off <<= 1) {
            int o = __shfl_up_sync(0xffffffffu, s, off);
            if (lane >= off) s += o;
        }
        if (lane == 31) sint[warp] = s;
        __syncthreads();
        if (t < 32) {
            int w2 = sint[t];
            #pragma unroll
            for (int off = 1; off < 32; off <<= 1) {
                int o = __shfl_up_sync(0xffffffffu, w2, off);
                if (t >= off) w2 += o;
            }
            sint[t] = w2;
        }
        __syncthreads();
        int incl = s + (warp ? sint[warp - 1] : 0);
        g_incl[i] = incl;
        if (t == NTHR - 1) g_btot[b] = incl;
    }
    gbar(gen);

    // ===== Phase B3: global offsets -> start/cursor =========================
    if (b < 16) {
        int off = 0;
        #pragma unroll
        for (int j = 0; j < 16; j++) if (j < b) off += g_btot[j];
        int i = b * NTHR + t;
        int excl = off + g_incl[i] - g_hist[i];
        g_start[i]  = excl;
        g_cursor[i] = excl;
    }
    if (b == 0 && t == 0) g_start[NB] = N;
    gbar(gen);

    // ===== Phase C: scatter (128 blocks x 64) + re-zero histogram ===========
    if (b < 128) {
        if (t < 64) {
            int i = b * 64 + t;
            unsigned u = g_ukey[i];
            int pos = atomicAdd(&g_cursor[u >> SHIFT], 1);
            g_bkey[pos] = u;
            g_bidx[pos] = i;
        } else if (t < 192) {
            g_hist[b * 128 + (t - 64)] = 0;
        }
    }
    gbar(gen);

    // ===== Phase D: rank within bucket (16 threads/element) =================
    {
        int el  = gtid >> 4;           // 0..8319
        int seg = gtid & 15;
        if (el < N) {
            unsigned u = g_bkey[el];
            int i  = g_bidx[el];
            int bk = u >> SHIFT;
            int st = g_start[bk], en = g_start[bk + 1];
            int rank = 0;
            for (int j = st + seg; j < en; j += 16) {
                unsigned kj = g_bkey[j];
                rank += (kj < u) || (kj == u && g_bidx[j] < i);
            }
            #pragma unroll
            for (int off = 8; off > 0; off >>= 1)
                rank += __shfl_down_sync(0xffffffffu, rank, off, 16);
            if (seg == 0) {
                rank += st;
                float f2v = g_f2[i];
                g_f2s[rank] = f2v;
                g_ord[rank] = i;
                g_ehi[rank] = expf(f2v);
                g_elo[rank] = expf(ALPHA * f2v);
            }
        }
    }
    gbar(gen);

    // ===== Phase D2: smem-tiled permuted transpose h -> g_hsT[d][k] =========
    if (b < 128) {
        float* tile = (float*)sbuf;                // [64][65]
        const int k0 = b * 64;
        if (t < 64) sord[t] = g_ord[k0 + t];
        __syncthreads();
        {
            int kk = t >> 4, l4 = (t & 15) * 4;    // coalesced-ish row load
            float4 hv = *(const float4*)&g_h[sord[kk] * D + l4];
            tile[kk * 65 + l4 + 0] = hv.x;
            tile[kk * 65 + l4 + 1] = hv.y;
            tile[kk * 65 + l4 + 2] = hv.z;
            tile[kk * 65 + l4 + 3] = hv.w;
        }
        __syncthreads();
        {
            int d = t >> 4, kq = (t & 15) * 4;     // coalesced write along k
            float4 ov = make_float4(tile[(kq + 0) * 65 + d],
                                    tile[(kq + 1) * 65 + d],
                                    tile[(kq + 2) * 65 + d],
                                    tile[(kq + 3) * 65 + d]);
            *(float4*)&g_hsT[d * N + k0 + kq] = ov;
        }
    }
    gbar(gen);

    // ===== Phase E: 130 directional fp64-accum scans -> TRANSPOSED fp32 =====
    // hi blocks (b<64 dims, b==128 scalar): SUFFIX -> g_SThi / g_pshis
    // lo blocks (64..127, b==129 scalar):  PREFIX -> g_STlo / g_pslos
    if (b < 130) {
        bool scalar = (b >= 128);
        bool hi = (b < 64) || (b == 128);
        int dim = scalar ? 0 : (hi ? b : b - 64);
        const float* e    = hi ? g_ehi : g_elo;
        const float* hrow = g_hsT + (size_t)dim * N;

        int k0 = t * 8;
        float ev[8], hv[8];
        *(float4*)&ev[0] = *(const float4*)&e[k0];       // vectorized loads
        *(float4*)&ev[4] = *(const float4*)&e[k0 + 4];
        if (!scalar) {
            *(float4*)&hv[0] = *(const float4*)&hrow[k0];
            *(float4*)&hv[4] = *(const float4*)&hrow[k0 + 4];
        } else {
            #pragma unroll
            for (int j = 0; j < 8; j++) hv[j] = 1.f;
        }

        double v[8];
        double run = 0.0;
        if (hi) {                      // local SUFFIX within chunk (j desc)
            #pragma unroll
            for (int j = 7; j >= 0; j--) {
                run += (double)ev[j] * (double)hv[j];
                v[j] = run;
            }
        } else {                       // local PREFIX within chunk (j asc)
            #pragma unroll
            for (int j = 0; j < 8; j++) {
                run += (double)ev[j] * (double)hv[j];
                v[j] = run;
            }
        }
        double w = run;
        if (hi) {                      // reverse inclusive scan across lanes
            #pragma unroll
            for (int off = 1; off < 32; off <<= 1) {
                double o = __shfl_down_sync(0xffffffffu, w, off);
                if (lane + off < 32) w += o;
            }
            if (lane == 0) sdbl[warp] = w;
            __syncthreads();
            if (t < 32) {
                double x2 = sdbl[t];
                #pragma unroll
                for (int off = 1; off < 32; off <<= 1) {
                    double o = __shfl_down_sync(0xffffffffu, x2, off);
                    if (t + off < 32) x2 += o;
                }
                sdbl[t] = x2;
            }
            __syncthreads();
            double base = (w - run) + (warp < 31 ? sdbl[warp + 1] : 0.0);
            if (scalar) {
                #pragma unroll
                for (int j = 0; j < 8; j++) g_pshis[k0 + j] = (float)(base + v[j]);
                if (t == 0) g_pshis[N] = 0.f;
            } else {
                float4 s0 = make_float4((float)(base + v[0]), (float)(base + v[1]),
                                        (float)(base + v[2]), (float)(base + v[3]));
                float4 s1 = make_float4((float)(base + v[4]), (float)(base + v[5]),
                                        (float)(base + v[6]), (float)(base + v[7]));
                *(float4*)&g_SThi[(size_t)dim * N + k0]     = s0;
                *(float4*)&g_SThi[(size_t)dim * N + k0 + 4] = s1;
            }
        } else {                       // forward inclusive scan across lanes
            #pragma unroll
            for (int off = 1; off < 32; off <<= 1) {
                double o = __shfl_up_sync(0xffffffffu, w, off);
                if (lane >= off) w += o;
            }
            if (lane == 31) sdbl[warp] = w;
            __syncthreads();
            if (t < 32) {
                double x2 = sdbl[t];
                #pragma unroll
                for (int off = 1; off < 32; off <<= 1) {
                    double o = __shfl_up_sync(0xffffffffu, x2, off);
                    if (t >= off) x2 += o;
                }
                sdbl[t] = x2;
            }
            __syncthreads();
            double base = (w - run) + (warp ? sdbl[warp - 1] : 0.0);
            if (scalar) {              // shifted: pslos[k+1] = incl prefix
                #pragma unroll
                for (int j = 0; j < 8; j++) g_pslos[k0 + j + 1] = (float)(base + v[j]);
                if (t == 0) g_pslos[0] = 0.f;
            } else {                   // unshifted transposed; shift applied in F
                float4 s0 = make_float4((float)(base + v[0]), (float)(base + v[1]),
                                        (float)(base + v[2]), (float)(base + v[3]));
                float4 s1 = make_float4((float)(base + v[4]), (float)(base + v[5]),
                                        (float)(base + v[6]), (float)(base + v[7]));
                *(float4*)&g_STlo[(size_t)dim * N + k0]     = s0;
                *(float4*)&g_STlo[(size_t)dim * N + k0 + 4] = s1;
            }
        }

        // per-row binary search (idle-lane work, independent of scan stores)
        if (t < 64 && b < 128) {
            int row = b * 64 + t;
            float f1 = g_f1[row];
            float tt = -f1;
            int lo = 0, hi2 = N;           // p = #{ f2s <= -f1 }
            while (lo < hi2) {
                int mid = (lo + hi2) >> 1;
                if (g_f2s[mid] <= tt) lo = mid + 1; else hi2 = mid;
            }
            g_p[row] = lo;
            g_c[row] = expf((ALPHA - 1.0f) * f1);
        }
    }
    gbar(gen);

    // ===== Phase F: tiled transpose [d][k] -> [k][d] (+ zero pad rows) ======
    {
        if (b == 128 && t < 64) g_Shi[N * D + t] = 0.f;   // Shi row N
        if (b == 129 && t < 64) g_Plo[t] = 0.f;           // Plo row 0
        float* tile = (float*)sbuf;                       // [64][65]
        for (int tile_id = b; tile_id < 256; tile_id += NBLK) {
            bool hiA = tile_id < 128;
            int k0 = (tile_id & 127) * 64;
            const float* src = hiA ? g_SThi : g_STlo;
            __syncthreads();                              // reuse guard
            {
                int d = t >> 4, kq = (t & 15) * 4;        // coalesced read along k
                float4 sv = *(const float4*)&src[(size_t)d * N + k0 + kq];
                tile[(kq + 0) * 65 + d] = sv.x;
                tile[(kq + 1) * 65 + d] = sv.y;
                tile[(kq + 2) * 65 + d] = sv.z;
                tile[(kq + 3) * 65 + d] = sv.w;
            }
            __syncthreads();
            {
                int kk = t >> 4, dq = (t & 15) * 4;       // coalesced write along d
                float4 ov = make_float4(tile[kk * 65 + dq + 0],
                                        tile[kk * 65 + dq + 1],
                                        tile[kk * 65 + dq + 2],
                                        tile[kk * 65 + dq + 3]);
                if (hiA) *(float4*)&g_Shi[(k0 + kk) * D + dq]     = ov;
                else     *(float4*)&g_Plo[(k0 + kk + 1) * D + dq] = ov;
            }
        }
    }
    gbar(gen);

    // ===== Phase G: branchless fp32 combine + ELU ===========================
    {
        const int d = gtid & 63;           // invariant: GSIZE % 64 == 0
        for (int idx = gtid; idx < N * D; idx += GSIZE) {
            int row = idx >> 6;
            int   p = g_p[row];
            float c = g_c[row];
            float num = g_Shi[p * D + d] + c * g_Plo[p * D + d];
            float den = g_pshis[p]       + c * g_pslos[p];
            float v = __fdividef(num, den);
            out[idx] = (v > 0.f) ? v : expm1f(v);
        }
    }
}

// ---------------- launch ----------------------------------------------------
extern "C" void kernel_launch(void* const* d_in, const int* in_sizes, int n_in,
                              void* d_out, int out_size) {
    const float* x  = (const float*)d_in[0];
    const float* Wt = (const float*)d_in[1];
    const float* a1 = (const float*)d_in[2];
    const float* b1 = (const float*)d_in[3];
    const float* a2 = (const float*)d_in[4];
    const float* b2 = (const float*)d_in[5];
    float* out = (float*)d_out;

    k_fused<<<NBLK, NTHR>>>(x, Wt, a1, b1, a2, b2, out);
}

// round 16
// speedup vs baseline: 1.6372x; 1.2656x over previous
#include <cuda_runtime.h>
#include <math.h>

#define N 8192
#define D 64
#define ALPHA 0.2f
#define NB 16384
#define SHIFT 18           // bucket = top 14 bits of order-flipped float key
#define NBLK 130
#define NTHR 1024
#define GSIZE (NBLK * NTHR)

// ---------------- scratch (device globals; no allocation allowed) -----------
__device__ float    g_h[N * D];        // projected features (2 MB)
__device__ float    g_hsT[D * N];      // h, sorted order, TRANSPOSED [d][k] (2 MB)
__device__ float    g_f1[N];
__device__ float    g_f2[N];
__device__ unsigned g_ukey[N];
__device__ int      g_hist[NB];
__device__ int      g_incl[NB];        // block-local inclusive scan of hist
__device__ int      g_btot[16];
__device__ int      g_start[NB + 1];
__device__ int      g_cursor[NB];
__device__ unsigned g_bkey[N];
__device__ int      g_bidx[N];
__device__ float    g_f2s[N];          // f2 sorted ascending
__device__ int      g_ord[N];          // sorted position -> original index
__device__ float    g_ehi[N];          // e^{f2s}
__device__ float    g_elo[N];          // e^{ALPHA*f2s}
__device__ int      g_p[N];            // per-row split point
__device__ float    g_c[N];            // per-row e^{(ALPHA-1) f1}
__device__ float    g_SThi[D * N];     // suffix sums, transposed [d][k] (2 MB)
__device__ float    g_STlo[D * N];     // prefix sums, transposed [d][k] (2 MB)
__device__ float    g_Shi[(N + 1) * D];// SUFFIX sums [k][d]; row N = 0
__device__ float    g_Plo[(N + 1) * D];// PREFIX sums shifted [k][d]; row 0 = 0
__device__ float    g_pshis[N + 1];    // scalar suffix of e^{f2};   [N]=0
__device__ float    g_pslos[N + 1];    // scalar prefix of e^{a f2}; [0]=0

// ---------------- software grid barrier -------------------------------------
__device__ unsigned g_bar_arrive = 0;
__device__ unsigned g_bar_gen    = 0;

__device__ __forceinline__ void gbar(unsigned& gen) {
    __syncthreads();
    if (threadIdx.x == 0) {
        __threadfence();
        unsigned my = gen;
        if (atomicAdd(&g_bar_arrive, 1) == NBLK - 1) {
            g_bar_arrive = 0;          // reset BEFORE release (ordered by fence)
            __threadfence();
            atomicAdd(&g_bar_gen, 1);
        } else {
            while (*(volatile unsigned*)&g_bar_gen == my) __nanosleep(32);
        }
        __threadfence();
        gen = my + 1;
    }
    __syncthreads();
}

// ---------------- the single persistent kernel ------------------------------
__global__ void __launch_bounds__(NTHR, 1) k_fused(
    const float* __restrict__ x,  const float* __restrict__ Wt,
    const float* __restrict__ a1, const float* __restrict__ b1,
    const float* __restrict__ a2, const float* __restrict__ b2,
    float* __restrict__ out)
{
    __shared__ __align__(16) char sbuf[35328];   // A: sWt|sxT|sa1|sa2|sred ; D2/F tile
    __shared__ int    sord[64];
    __shared__ int    sint[32];
    __shared__ float  sflt[32];

    const int t    = threadIdx.x;
    const int b    = blockIdx.x;
    const int gtid = b * NTHR + t;
    const int lane = t & 31, warp = t >> 5;
    unsigned gen = *(volatile unsigned*)&g_bar_gen;   // per-launch snapshot

    // ===== Phase A: projection h = x*Wt, scores f1/f2, key + histogram ======
    // sxT[k][r] (pad 68): per k-iter the x-quad is a 16B warp-broadcast and
    // the w-read is conflict-free 128B — ~2 LDS-cyc per 4 FMA.
    if (b < 128) {
        float* sWt   = (float*)sbuf;                  // [64][64]  16384 B
        float* sxT   = (float*)(sbuf + 16384);        // [64][68]  17408 B
        float* sa1   = (float*)(sbuf + 33792);        // 256 B
        float* sa2   = (float*)(sbuf + 34048);        // 256 B
        float* sred1 = (float*)(sbuf + 34304);        // [32 warps][4 rows]
        float* sred2 = (float*)(sbuf + 34816);
        const int row0 = b * 64;

        for (int i = t; i < D * D; i += NTHR) sWt[i] = Wt[i];
        for (int i = t; i < D * D; i += NTHR) {
            int r = i >> 6, k = i & 63;
            sxT[k * 68 + r] = x[row0 * D + i];
        }
        if (t < D) { sa1[t] = a1[t]; sa2[t] = a2[t]; }
        __syncthreads();

        const int c  = t & 63;                  // output column
        const int rq = (t >> 6) * 4;            // row-quad base (0,4,...,60)

        float acc0 = 0.f, acc1 = 0.f, acc2 = 0.f, acc3 = 0.f;
        #pragma unroll 16
        for (int k = 0; k < D; k++) {
            float  wv = sWt[k * D + c];                    // conflict-free
            float4 xv = *(const float4*)&sxT[k * 68 + rq]; // 16B broadcast
            acc0 = fmaf(xv.x, wv, acc0);
            acc1 = fmaf(xv.y, wv, acc1);
            acc2 = fmaf(xv.z, wv, acc2);
            acc3 = fmaf(xv.w, wv, acc3);
        }
        g_h[(row0 + rq + 0) * D + c] = acc0;    // coalesced per row
        g_h[(row0 + rq + 1) * D + c] = acc1;
        g_h[(row0 + rq + 2) * D + c] = acc2;
        g_h[(row0 + rq + 3) * D + c] = acc3;

        float a1c = sa1[c], a2c = sa2[c];
        float q10 = acc0 * a1c, q11 = acc1 * a1c, q12 = acc2 * a1c, q13 = acc3 * a1c;
        float q20 = acc0 * a2c, q21 = acc1 * a2c, q22 = acc2 * a2c, q23 = acc3 * a2c;
        #pragma unroll
        for (int off = 16; off > 0; off >>= 1) {
            q10 += __shfl_down_sync(0xffffffffu, q10, off);
            q11 += __shfl_down_sync(0xffffffffu, q11, off);
            q12 += __shfl_down_sync(0xffffffffu, q12, off);
            q13 += __shfl_down_sync(0xffffffffu, q13, off);
            q20 += __shfl_down_sync(0xffffffffu, q20, off);
            q21 += __shfl_down_sync(0xffffffffu, q21, off);
            q22 += __shfl_down_sync(0xffffffffu, q22, off);
            q23 += __shfl_down_sync(0xffffffffu, q23, off);
        }
        if (lane == 0) {
            sred1[warp * 4 + 0] = q10; sred1[warp * 4 + 1] = q11;
            sred1[warp * 4 + 2] = q12; sred1[warp * 4 + 3] = q13;
            sred2[warp * 4 + 0] = q20; sred2[warp * 4 + 1] = q21;
            sred2[warp * 4 + 2] = q22; sred2[warp * 4 + 3] = q23;
        }
        __syncthreads();
        if (t < 64) {
            int rg = t >> 2, rr = t & 3;        // row = rg*4 + rr
            int w0 = rg * 2, w1 = w0 + 1;       // the two warps covering c 0..63
            float f1v = sred1[w0 * 4 + rr] + sred1[w1 * 4 + rr] + b1[0];
            float f2v = sred2[w0 * 4 + rr] + sred2[w1 * 4 + rr] + b2[0];
            int row = row0 + rg * 4 + rr;
            g_f1[row] = f1v;
            g_f2[row] = f2v;
            unsigned u = __float_as_uint(f2v);
            u ^= (u >> 31) ? 0xFFFFFFFFu : 0x80000000u;
            g_ukey[row] = u;
            atomicAdd(&g_hist[u >> SHIFT], 1);
        }
    }
    gbar(gen);

    // ===== Phase B1: per-block inclusive scan of histogram (16 blocks) ======
    if (b < 16) {
        int i = b * NTHR + t;
        int v = g_hist[i];
        int s = v;
        #pragma unroll
        for (int off = 1; off < 32; off <<= 1) {
            int o = __shfl_up_sync(0xffffffffu, s, off);
            if (lane >= off) s += o;
        }
        if (lane == 31) sint[warp] = s;
        __syncthreads();
        if (t < 32) {
            int w2 = sint[t];
            #pragma unroll
            for (int off = 1; off < 32; off <<= 1) {
                int o = __shfl_up_sync(0xffffffffu, w2, off);
                if (t >= off) w2 += o;
            }
            sint[t] = w2;
        }
        __syncthreads();
        int incl = s + (warp ? sint[warp - 1] : 0);
        g_incl[i] = incl;
        if (t == NTHR - 1) g_btot[b] = incl;
    }
    gbar(gen);

    // ===== Phase B3: global offsets -> start/cursor =========================
    if (b < 16) {
        int off = 0;
        #pragma unroll
        for (int j = 0; j < 16; j++) if (j < b) off += g_btot[j];
        int i = b * NTHR + t;
        int excl = off + g_incl[i] - g_hist[i];
        g_start[i]  = excl;
        g_cursor[i] = excl;
    }
    if (b == 0 && t == 0) g_start[NB] = N;
    gbar(gen);

    // ===== Phase C: scatter (128 blocks x 64) + re-zero histogram ===========
    if (b < 128) {
        if (t < 64) {
            int i = b * 64 + t;
            unsigned u = g_ukey[i];
            int pos = atomicAdd(&g_cursor[u >> SHIFT], 1);
            g_bkey[pos] = u;
            g_bidx[pos] = i;
        } else if (t < 192) {
            g_hist[b * 128 + (t - 64)] = 0;
        }
    }
    gbar(gen);

    // ===== Phase D: rank within bucket (16 threads/element) =================
    {
        int el  = gtid >> 4;           // 0..8319
        int seg = gtid & 15;
        if (el < N) {
            unsigned u = g_bkey[el];
            int i  = g_bidx[el];
            int bk = u >> SHIFT;
            int st = g_start[bk], en = g_start[bk + 1];
            int rank = 0;
            for (int j = st + seg; j < en; j += 16) {
                unsigned kj = g_bkey[j];
                rank += (kj < u) || (kj == u && g_bidx[j] < i);
            }
            #pragma unroll
            for (int off = 8; off > 0; off >>= 1)
                rank += __shfl_down_sync(0xffffffffu, rank, off, 16);
            if (seg == 0) {
                rank += st;
                float f2v = g_f2[i];
                g_f2s[rank] = f2v;
                g_ord[rank] = i;
                g_ehi[rank] = expf(f2v);
                g_elo[rank] = expf(ALPHA * f2v);
            }
        }
    }
    gbar(gen);

    // ===== Phase D2: smem-tiled permuted transpose h -> g_hsT[d][k] =========
    if (b < 128) {
        float* tile = (float*)sbuf;                // [64][65]
        const int k0 = b * 64;
        if (t < 64) sord[t] = g_ord[k0 + t];
        __syncthreads();
        {
            int kk = t >> 4, l4 = (t & 15) * 4;    // coalesced-ish row load
            float4 hv = *(const float4*)&g_h[sord[kk] * D + l4];
            tile[kk * 65 + l4 + 0] = hv.x;
            tile[kk * 65 + l4 + 1] = hv.y;
            tile[kk * 65 + l4 + 2] = hv.z;
            tile[kk * 65 + l4 + 3] = hv.w;
        }
        __syncthreads();
        {
            int d = t >> 4, kq = (t & 15) * 4;     // coalesced write along k
            float4 ov = make_float4(tile[(kq + 0) * 65 + d],
                                    tile[(kq + 1) * 65 + d],
                                    tile[(kq + 2) * 65 + d],
                                    tile[(kq + 3) * 65 + d]);
            *(float4*)&g_hsT[d * N + k0 + kq] = ov;
        }
    }
    gbar(gen);

    // ===== Phase E: 130 directional fp32 scans -> TRANSPOSED layout =========
    // All-positive accumulation (no cancellation): fp32 chunk+tree scan has
    // ~sqrt(N)*eps ~ 5e-6 rel err — 100x inside the 1e-3 budget.
    // hi blocks (b<64 dims, b==128 scalar): SUFFIX -> g_SThi / g_pshis
    // lo blocks (64..127, b==129 scalar):  PREFIX -> g_STlo / g_pslos
    if (b < 130) {
        bool scalar = (b >= 128);
        bool hi = (b < 64) || (b == 128);
        int dim = scalar ? 0 : (hi ? b : b - 64);
        const float* e    = hi ? g_ehi : g_elo;
        const float* hrow = g_hsT + (size_t)dim * N;

        int k0 = t * 8;
        float ev[8], hv[8];
        *(float4*)&ev[0] = *(const float4*)&e[k0];       // vectorized loads
        *(float4*)&ev[4] = *(const float4*)&e[k0 + 4];
        if (!scalar) {
            *(float4*)&hv[0] = *(const float4*)&hrow[k0];
            *(float4*)&hv[4] = *(const float4*)&hrow[k0 + 4];
        } else {
            #pragma unroll
            for (int j = 0; j < 8; j++) hv[j] = 1.f;
        }

        float v[8];
        float run = 0.f;
        if (hi) {                      // local SUFFIX within chunk (j desc)
            #pragma unroll
            for (int j = 7; j >= 0; j--) {
                run = fmaf(ev[j], hv[j], run);
                v[j] = run;
            }
        } else {                       // local PREFIX within chunk (j asc)
            #pragma unroll
            for (int j = 0; j < 8; j++) {
                run = fmaf(ev[j], hv[j], run);
                v[j] = run;
            }
        }
        float w = run;
        if (hi) {                      // reverse inclusive scan across lanes
            #pragma unroll
            for (int off = 1; off < 32; off <<= 1) {
                float o = __shfl_down_sync(0xffffffffu, w, off);
                if (lane + off < 32) w += o;
            }
            if (lane == 0) sflt[warp] = w;
            __syncthreads();
            if (t < 32) {
                float x2 = sflt[t];
                #pragma unroll
                for (int off = 1; off < 32; off <<= 1) {
                    float o = __shfl_down_sync(0xffffffffu, x2, off);
                    if (t + off < 32) x2 += o;
                }
                sflt[t] = x2;
            }
            __syncthreads();
            float base = (w - run) + (warp < 31 ? sflt[warp + 1] : 0.f);
            if (scalar) {
                #pragma unroll
                for (int j = 0; j < 8; j++) g_pshis[k0 + j] = base + v[j];
                if (t == 0) g_pshis[N] = 0.f;
            } else {
                float4 s0 = make_float4(base + v[0], base + v[1],
                                        base + v[2], base + v[3]);
                float4 s1 = make_float4(base + v[4], base + v[5],
                                        base + v[6], base + v[7]);
                *(float4*)&g_SThi[(size_t)dim * N + k0]     = s0;
                *(float4*)&g_SThi[(size_t)dim * N + k0 + 4] = s1;
            }
        } else {                       // forward inclusive scan across lanes
            #pragma unroll
            for (int off = 1; off < 32; off <<= 1) {
                float o = __shfl_up_sync(0xffffffffu, w, off);
                if (lane >= off) w += o;
            }
            if (lane == 31) sflt[warp] = w;
            __syncthreads();
            if (t < 32) {
                float x2 = sflt[t];
                #pragma unroll
                for (int off = 1; off < 32; off <<= 1) {
                    float o = __shfl_up_sync(0xffffffffu, x2, off);
                    if (t >= off) x2 += o;
                }
                sflt[t] = x2;
            }
            __syncthreads();
            float base = (w - run) + (warp ? sflt[warp - 1] : 0.f);
            if (scalar) {              // shifted: pslos[k+1] = incl prefix
                #pragma unroll
                for (int j = 0; j < 8; j++) g_pslos[k0 + j + 1] = base + v[j];
                if (t == 0) g_pslos[0] = 0.f;
            } else {                   // unshifted transposed; shift applied in F
                float4 s0 = make_float4(base + v[0], base + v[1],
                                        base + v[2], base + v[3]);
                float4 s1 = make_float4(base + v[4], base + v[5],
                                        base + v[6], base + v[7]);
                *(float4*)&g_STlo[(size_t)dim * N + k0]     = s0;
                *(float4*)&g_STlo[(size_t)dim * N + k0 + 4] = s1;
            }
        }

        // per-row binary search (idle-lane work, independent of scan stores)
        if (t < 64 && b < 128) {
            int row = b * 64 + t;
            float f1 = g_f1[row];
            float tt = -f1;
            int lo = 0, hi2 = N;           // p = #{ f2s <= -f1 }
            while (lo < hi2) {
                int mid = (lo + hi2) >> 1;
                if (g_f2s[mid] <= tt) lo = mid + 1; else hi2 = mid;
            }
            g_p[row] = lo;
            g_c[row] = expf((ALPHA - 1.0f) * f1);
        }
    }
    gbar(gen);

    // ===== Phase F: tiled transpose [d][k] -> [k][d] (+ zero pad rows) ======
    {
        if (b == 128 && t < 64) g_Shi[N * D + t] = 0.f;   // Shi row N
        if (b == 129 && t < 64) g_Plo[t] = 0.f;           // Plo row 0
        float* tile = (float*)sbuf;                       // [64][65]
        for (int tile_id = b; tile_id < 256; tile_id += NBLK) {
            bool hiA = tile_id < 128;
            int k0 = (tile_id & 127) * 64;
            const float* src = hiA ? g_SThi : g_STlo;
            __syncthreads();                              // reuse guard
            {
                int d = t >> 4, kq = (t & 15) * 4;        // coalesced read along k
                float4 sv = *(const float4*)&src[(size_t)d * N + k0 + kq];
                tile[(kq + 0) * 65 + d] = sv.x;
                tile[(kq + 1) * 65 + d] = sv.y;
                tile[(kq + 2) * 65 + d] = sv.z;
                tile[(kq + 3) * 65 + d] = sv.w;
            }
            __syncthreads();
            {
                int kk = t >> 4, dq = (t & 15) * 4;       // coalesced write along d
                float4 ov = make_float4(tile[kk * 65 + dq + 0],
                                        tile[kk * 65 + dq + 1],
                                        tile[kk * 65 + dq + 2],
                                        tile[kk * 65 + dq + 3]);
                if (hiA) *(float4*)&g_Shi[(k0 + kk) * D + dq]     = ov;
                else     *(float4*)&g_Plo[(k0 + kk + 1) * D + dq] = ov;
            }
        }
    }
    gbar(gen);

    // ===== Phase G: branchless fp32 combine + ELU ===========================
    {
        const int d = gtid & 63;           // invariant: GSIZE % 64 == 0
        for (int idx = gtid; idx < N * D; idx += GSIZE) {
            int row = idx >> 6;
            int   p = g_p[row];
            float c = g_c[row];
            float num = g_Shi[p * D + d] + c * g_Plo[p * D + d];
            float den = g_pshis[p]       + c * g_pslos[p];
            float v = __fdividef(num, den);
            out[idx] = (v > 0.f) ? v : expm1f(v);
        }
    }
}

// ---------------- launch ----------------------------------------------------
extern "C" void kernel_launch(void* const* d_in, const int* in_sizes, int n_in,
                              void* d_out, int out_size) {
    const float* x  = (const float*)d_in[0];
    const float* Wt = (const float*)d_in[1];
    const float* a1 = (const float*)d_in[2];
    const float* b1 = (const float*)d_in[3];
    const float* a2 = (const float*)d_in[4];
    const float* b2 = (const float*)d_in[5];
    float* out = (float*)d_out;

    k_fused<<<NBLK, NTHR>>>(x, Wt, a1, b1, a2, b2, out);
}